// round 5
// baseline (speedup 1.0000x reference)
#include <cuda_runtime.h>
#include <math.h>

// BalancedAveragedHausdorffLoss, single fused kernel.
// B=8, C=4, H=W=64 -> N=32 items. One block per (item, direction) = 64 blocks.
//
// EDT phase 1: column bitmasks (64-bit) + clz/ffs nearest-set-bit -> fully
// parallel. Phase 2: packed s16x2 SIMD row scan (values <= 63^2+127^2 < 2^15),
// add-only recurrence (PTX has no sub.s16x2). Finalize fused via
// threadfence + atomic counter (reset for graph replay determinism).

#define ITEMS 32
#define Wdim  64
#define HW    4096
#define GINF  127   // 127^2 = 16129; +63^2 = 20098 < 32768 (fits s16)

__device__ float        g_terms[2 * ITEMS];
__device__ int          g_counts[2 * ITEMS];
__device__ unsigned int g_done;   // starts 0, reset to 0 by last block

__device__ __forceinline__ int vadd16x2(int a, int b) {
    int r; asm("add.s16x2 %0,%1,%2;" : "=r"(r) : "r"(a), "r"(b)); return r;
}
__device__ __forceinline__ int vmin16x2(int a, int b) {
    int r; asm("min.s16x2 %0,%1,%2;" : "=r"(r) : "r"(a), "r"(b)); return r;
}

// nearest-set-bit distance from row x in 64-bit column mask M (GINF if none)
__device__ __forceinline__ int bitdist(unsigned long long M, int x) {
    unsigned long long U = M >> x;                 // bits at rows >= x
    unsigned long long V = M << (63 - x);          // bits at rows <= x
    int dDown = U ? (__ffsll((long long)U) - 1) : GINF;
    int dUp   = V ? __clzll((long long)V)      : GINF;
    return min(dDown, dUp);
}

__global__ __launch_bounds__(256)
void bahl_fused_kernel(const float* __restrict__ pred,
                       const float* __restrict__ target,
                       float* __restrict__ out)
{
    __shared__ unsigned long long colmask[Wdim];   // src-mask bits per column
    __shared__ int   g2p[Wdim * 32];               // packed (g2[x][yp], g2[x][yp+32])
    __shared__ float sacc[8];
    __shared__ int   sct[8], scp[8];

    const int bi    = blockIdx.x;
    const int item  = bi >> 1;
    const int which = bi & 1;
    const int tid   = threadIdx.x;

    const float* pb = pred   + item * HW;
    const float* tb = target + item * HW;

    if (tid < Wdim) colmask[tid] = 0ULL;
    __syncthreads();

    // --- Load: masks, counts, per-thread dst bits, src column bitmasks ---
    const float THR = 0.30001f;
    int ct = 0, cp = 0;
    unsigned int dmask = 0;   // bit k -> pixel tid + k*256 is in dst mask
    #pragma unroll
    for (int k = 0; k < 16; k++) {
        const int i = tid + k * 256;
        const int x = i >> 6, y = i & 63;
        float pv = pb[i];
        float tv = tb[i];
        int pm = (fabsf(pv - 1.0f) <= THR) ? 1 : 0;
        int tm = (tv != 0.0f) ? 1 : 0;
        ct += tm; cp += pm;
        int src = which ? pm : tm;
        int dst = which ? tm : pm;
        dmask |= ((unsigned)dst) << k;
        if (src) atomicOr(&colmask[y], 1ULL << x);   // warp-conflict-free (y distinct)
    }
    __syncthreads();

    // --- Phase 1 (parallel): packed squared vertical distances ----------
    // entry (x, yp) packs g^2 for columns yp and yp+32 at row x.
    #pragma unroll
    for (int k = 0; k < 8; k++) {
        const int idx = tid + k * 256;        // 0..2047
        const int x  = idx >> 5;
        const int yp = idx & 31;
        int g1 = bitdist(colmask[yp],      x);
        int g2 = bitdist(colmask[yp + 32], x);
        g2p[idx] = (g1 * g1) | ((g2 * g2) << 16);
    }
    __syncthreads();

    // --- Phase 2: per-pixel min over row, s16x2 SIMD (add-only) ---------
    float acc = 0.0f;
    #pragma unroll
    for (int k = 0; k < 16; k++) {
        const int pix = tid + k * 256;
        const int row = pix >> 6;
        const int y   = pix & 63;
        const int* __restrict__ grow = &g2p[row * 32];
        // lanes: (dy1 = y - yp, dy2 = y - 32 - yp), yp increasing
        int dy1 = y, dy2 = y - 32;
        int d2 = (dy1 * dy1) | ((dy2 * dy2) << 16);
        // add-only recurrence: (dy-1)^2 = dy^2 + (1 - 2*dy); t += 2
        int t  = ((1 - 2 * dy1) & 0xffff) | (((unsigned)(1 - 2 * dy2) & 0xffffu) << 16);
        const int two = 0x00020002;
        int rmin = 0x7FFF7FFF;
        #pragma unroll
        for (int yp = 0; yp < 32; yp++) {
            rmin = vmin16x2(rmin, vadd16x2(d2, grow[yp]));
            d2   = vadd16x2(d2, t);
            t    = vadd16x2(t, two);
        }
        int dmin = min(rmin & 0xffff, (rmin >> 16) & 0xffff);
        if ((dmask >> k) & 1u) acc += sqrtf((float)dmin);
    }

    // --- Block reduction ------------------------------------------------
    #pragma unroll
    for (int o = 16; o > 0; o >>= 1) {
        acc += __shfl_xor_sync(0xffffffffu, acc, o);
        ct  += __shfl_xor_sync(0xffffffffu, ct,  o);
        cp  += __shfl_xor_sync(0xffffffffu, cp,  o);
    }
    const int wid = tid >> 5, lid = tid & 31;
    if (lid == 0) { sacc[wid] = acc; sct[wid] = ct; scp[wid] = cp; }
    __syncthreads();

    if (tid == 0) {
        float a = 0.0f; int t = 0, p = 0;
        #pragma unroll
        for (int w = 0; w < 8; w++) { a += sacc[w]; t += sct[w]; p += scp[w]; }
        g_terms[bi] = a;
        if (which == 0) {
            g_counts[2 * item]     = t;   // n_t
            g_counts[2 * item + 1] = p;   // n_p
        }
        __threadfence();
        unsigned old = atomicAdd(&g_done, 1u);
        if (old == 2 * ITEMS - 1) {
            // last block: finalize (reads ordered after all fences via atomic)
            volatile float* vt = g_terms;
            volatile int*   vc = g_counts;
            float total = 0.0f;
            #pragma unroll 1
            for (int i = 0; i < ITEMS; i++) {
                float t1 = vt[2 * i], t2 = vt[2 * i + 1];
                int   nt = vc[2 * i], np = vc[2 * i + 1];
                if (nt > 0 && np > 0) total += (t1 + t2) / (2.0f * (float)nt);
            }
            out[0] = total / (float)ITEMS;
            __threadfence();
            g_done = 0;                   // reset for next graph replay
        }
    }
}

extern "C" void kernel_launch(void* const* d_in, const int* in_sizes, int n_in,
                              void* d_out, int out_size)
{
    const float* pred   = (const float*)d_in[0];
    const float* target = (const float*)d_in[1];
    float* out = (float*)d_out;
    (void)in_sizes; (void)n_in; (void)out_size;

    bahl_fused_kernel<<<2 * ITEMS, 256>>>(pred, target, out);
}

// round 6
// speedup vs baseline: 1.1495x; 1.1495x over previous
#include <cuda_runtime.h>
#include <math.h>

// BalancedAveragedHausdorffLoss, single fused kernel, v3.
// 128 blocks: (item, which, half). Row-mask build via ballot (no atomics),
// horizontal bitdist phase 1, vertical s16x2 SIMD phase 2 (add-only).
// Fused finalize via threadfence + atomic counter (reset each replay).

#define ITEMS 32
#define Wdim  64
#define HW    4096
#define GINF  127   // 127^2 + 63^2 = 20098 < 32768 (fits s16)

__device__ float        g_terms[4 * ITEMS];   // [item*4 + which*2 + half]
__device__ int          g_ct[2 * ITEMS];      // target count  [item*2 + half]
__device__ int          g_cp[2 * ITEMS];      // pred   count  [item*2 + half]
__device__ unsigned int g_done;               // 0 at start; reset by last block

__device__ __forceinline__ int vadd16x2(int a, int b) {
    int r; asm("add.s16x2 %0,%1,%2;" : "=r"(r) : "r"(a), "r"(b)); return r;
}
__device__ __forceinline__ int vmin16x2(int a, int b) {
    int r; asm("min.s16x2 %0,%1,%2;" : "=r"(r) : "r"(a), "r"(b)); return r;
}

// nearest-set-bit distance from position p in 64-bit mask M (GINF if none)
__device__ __forceinline__ int bitdist(unsigned long long M, int p) {
    unsigned long long U = M >> p;
    unsigned long long V = M << (63 - p);
    int dDown = U ? (__ffsll((long long)U) - 1) : GINF;
    int dUp   = V ? __clzll((long long)V)      : GINF;
    return min(dDown, dUp);
}

__global__ __launch_bounds__(256)
void bahl_fused_kernel(const float* __restrict__ pred,
                       const float* __restrict__ target,
                       float* __restrict__ out)
{
    __shared__ unsigned long long rmask[Wdim];   // src-mask bits over y, per row x
    __shared__ int   g2p[32 * Wdim];             // [xp][y] packed (h2[xp], h2[xp+32])
    __shared__ float sacc[8];
    __shared__ int   ssc[8], sdc[8];

    const int bi    = blockIdx.x;
    const int item  = bi >> 2;
    const int which = (bi >> 1) & 1;
    const int half  = bi & 1;
    const int tid   = threadIdx.x;

    const float* pb = pred   + item * HW;
    const float* tb = target + item * HW;
    const float* srcA = which ? pb : tb;   // which==0: src = target
    const float* dstA = which ? tb : pb;
    const bool srcIsTarget = (which == 0);
    const float THR = 0.30001f;

    // --- Loop A: full src scan -> rowmask via ballot + src count on our half
    int srcCount = 0;
    #pragma unroll
    for (int k = 0; k < 16; k++) {
        const int pix = tid + k * 256;
        float v = srcA[pix];
        bool bit = srcIsTarget ? (v != 0.0f) : (fabsf(v - 1.0f) <= THR);
        unsigned bal = __ballot_sync(0xffffffffu, bit);
        if ((tid & 31) == 0) ((unsigned*)rmask)[pix >> 5] = bal;
        if ((pix >> 11) == half) srcCount += bit ? 1 : 0;
    }

    // --- Loop B: dst scan on our half -> dst bits + count ---------------
    const int pbase = half * 2048;
    int dstCount = 0;
    unsigned dmask = 0;
    #pragma unroll
    for (int j = 0; j < 8; j++) {
        const int pix = pbase + tid + j * 256;
        float v = dstA[pix];
        bool bit = srcIsTarget ? (fabsf(v - 1.0f) <= THR) : (v != 0.0f);
        dmask |= (bit ? 1u : 0u) << j;
        dstCount += bit ? 1 : 0;
    }
    __syncthreads();   // rmask complete

    // --- Phase 1: horizontal squared distances h2[x][y], packed (xp, xp+32)
    #pragma unroll
    for (int j = 0; j < 8; j++) {
        const int idx = tid + j * 256;     // 0..2047
        const int xp  = idx >> 6;          // 0..31
        const int y   = idx & 63;
        int h1 = bitdist(rmask[xp],      y);
        int h2 = bitdist(rmask[xp + 32], y);
        g2p[idx] = (h1 * h1) | ((h2 * h2) << 16);
    }
    __syncthreads();

    // --- Phase 2: vertical s16x2 scan over 32 packed rows ---------------
    float acc = 0.0f;
    #pragma unroll
    for (int j = 0; j < 8; j++) {
        const int pix = pbase + tid + j * 256;
        const int x = pix >> 6;
        const int y = pix & 63;
        // lanes: dx1 = x - xp, dx2 = x - 32 - xp, xp increasing
        int dx1 = x, dx2 = x - 32;
        int d2 = (dx1 * dx1) | ((dx2 * dx2) << 16);
        int t  = ((1 - 2 * dx1) & 0xffff) | (((unsigned)(1 - 2 * dx2) & 0xffffu) << 16);
        const int two = 0x00020002;
        int rmin = 0x7FFF7FFF;
        const int* __restrict__ gcol = &g2p[y];
        #pragma unroll
        for (int xp = 0; xp < 32; xp++) {
            rmin = vmin16x2(rmin, vadd16x2(d2, gcol[xp * Wdim]));
            d2   = vadd16x2(d2, t);
            t    = vadd16x2(t, two);
        }
        int dmin = min(rmin & 0xffff, (rmin >> 16) & 0xffff);
        if ((dmask >> j) & 1u) acc += sqrtf((float)dmin);
    }

    // --- Block reduction -------------------------------------------------
    #pragma unroll
    for (int o = 16; o > 0; o >>= 1) {
        acc      += __shfl_xor_sync(0xffffffffu, acc,      o);
        srcCount += __shfl_xor_sync(0xffffffffu, srcCount, o);
        dstCount += __shfl_xor_sync(0xffffffffu, dstCount, o);
    }
    const int wid = tid >> 5, lid = tid & 31;
    if (lid == 0) { sacc[wid] = acc; ssc[wid] = srcCount; sdc[wid] = dstCount; }
    __syncthreads();

    if (tid == 0) {
        float a = 0.0f; int s = 0, d = 0;
        #pragma unroll
        for (int w = 0; w < 8; w++) { a += sacc[w]; s += ssc[w]; d += sdc[w]; }
        g_terms[bi] = a;
        if (which == 0) {                  // src=target, dst=pred
            g_ct[item * 2 + half] = s;     // n_t (this half)
            g_cp[item * 2 + half] = d;     // n_p (this half)
        }
        __threadfence();
        unsigned old = atomicAdd(&g_done, 1u);
        if (old == 4 * ITEMS - 1) {
            volatile float* vt = g_terms;
            volatile int*   vct = g_ct;
            volatile int*   vcp = g_cp;
            float total = 0.0f;
            #pragma unroll 1
            for (int i = 0; i < ITEMS; i++) {
                int   nt = vct[2 * i] + vct[2 * i + 1];
                int   np = vcp[2 * i] + vcp[2 * i + 1];
                float t1 = vt[4 * i]     + vt[4 * i + 1];
                float t2 = vt[4 * i + 2] + vt[4 * i + 3];
                if (nt > 0 && np > 0) total += (t1 + t2) / (2.0f * (float)nt);
            }
            out[0] = total / (float)ITEMS;
            __threadfence();
            g_done = 0;                    // reset for next graph replay
        }
    }
}

extern "C" void kernel_launch(void* const* d_in, const int* in_sizes, int n_in,
                              void* d_out, int out_size)
{
    const float* pred   = (const float*)d_in[0];
    const float* target = (const float*)d_in[1];
    float* out = (float*)d_out;
    (void)in_sizes; (void)n_in; (void)out_size;

    bahl_fused_kernel<<<4 * ITEMS, 256>>>(pred, target, out);
}